// round 10
// baseline (speedup 1.0000x reference)
#include <cuda_runtime.h>
#include <cstdint>

// Problem constants (fixed by setup_inputs): B=96, N_NODE=512, D=128, n_steps=5
#define NB 96
#define NN 512
#define ND 128
#define NROWS (NB * NN)            // 49152
#define NSTEPS 5

// Scratch (allocation-free rule: __device__ globals)
__device__ float g_hp[NROWS * ND];      // h @ Wp^T  [node][feat]
__device__ float g_neigh[NROWS * ND];   // mask @ hp + 512*bp
__device__ float g_Wt[7 * ND * ND];     // transposed weights: [k][j] = W[j][k]
// order: 0=Wz 1=Uz 2=Wr 3=Ur 4=Wh 5=Uh 6=Wp

typedef unsigned long long ull;

__device__ __forceinline__ ull pack2(float lo, float hi) {
    ull r; asm("mov.b64 %0, {%1,%2};" : "=l"(r) : "f"(lo), "f"(hi)); return r;
}
__device__ __forceinline__ void fma2(ull& d, ull a, ull b) {
    asm("fma.rn.f32x2 %0, %1, %2, %0;" : "+l"(d) : "l"(a), "l"(b));
}
__device__ __forceinline__ void unpack2(ull v, float& lo, float& hi) {
    asm("mov.b64 {%0,%1}, %2;" : "=f"(lo), "=f"(hi) : "l"(v));
}
__device__ __forceinline__ float sigmoidf_(float x) { return 1.0f / (1.0f + __expf(-x)); }
__device__ __forceinline__ uint32_t s2u(const void* p) {
    uint32_t a;
    asm("{ .reg .u64 t; cvta.to.shared.u64 t, %1; cvt.u32.u64 %0, t; }" : "=r"(a) : "l"(p));
    return a;
}
__device__ __forceinline__ void cp16(float* dst, const float* src) {
    asm volatile("cp.async.cg.shared.global [%0], [%1], 16;" :: "r"(s2u(dst)), "l"(src));
}
#define CP_COMMIT() asm volatile("cp.async.commit_group;")
#define CP_WAIT(n)  asm volatile("cp.async.wait_group %0;" :: "n"(n))

__device__ __forceinline__ int colof(int c0, int j) { return (j < 4) ? (c0 + j) : (c0 + 60 + j); }

// ---------------------------------------------------------------------------
// Generic micro-kernel: thread computes MT rows x 8 cols over KTOT k-steps.
// sX: [rows][LDA] (k contig). sW: [KTOT k][LDW] (col contig).
// cols = c0+{0..3}, c0+64+{0..3}. A-loads: 2 addrs/warp (broadcast).
// W-loads: within one k-row, 16 distinct 16B addrs — no conflicts.
// ---------------------------------------------------------------------------
template <int MT, int KTOT, int LDA, int LDW>
__device__ __forceinline__ void mma_t(const float* __restrict__ sX,
                                      const float* __restrict__ sW,
                                      int r0, int c0, ull acc[MT][4]) {
#pragma unroll 2
    for (int k = 0; k < KTOT; k += 4) {
        float4 a[MT];
#pragma unroll
        for (int i = 0; i < MT; i++)
            a[i] = *(const float4*)(sX + (r0 + i) * LDA + k);
#pragma unroll
        for (int kk = 0; kk < 4; kk++) {
            const float* wr = sW + (k + kk) * LDW;
            float4 w0 = *(const float4*)(wr + c0);
            float4 w1 = *(const float4*)(wr + c0 + 64);
            ull wp0 = pack2(w0.x, w0.y), wp1 = pack2(w0.z, w0.w);
            ull wp2 = pack2(w1.x, w1.y), wp3 = pack2(w1.z, w1.w);
#pragma unroll
            for (int i = 0; i < MT; i++) {
                float e = (kk == 0) ? a[i].x : (kk == 1) ? a[i].y : (kk == 2) ? a[i].z : a[i].w;
                ull ap = pack2(e, e);
                fma2(acc[i][0], ap, wp0); fma2(acc[i][1], ap, wp1);
                fma2(acc[i][2], ap, wp2); fma2(acc[i][3], ap, wp3);
            }
        }
    }
}
template <int MT>
__device__ __forceinline__ void zacc(ull acc[MT][4]) {
#pragma unroll
    for (int i = 0; i < MT; i++)
#pragma unroll
        for (int p = 0; p < 4; p++) acc[i][p] = 0ull;
}
__device__ __forceinline__ void row_f8(const ull a[4], float o[8]) {
    unpack2(a[0], o[0], o[1]); unpack2(a[1], o[2], o[3]);
    unpack2(a[2], o[4], o[5]); unpack2(a[3], o[6], o[7]);
}

// cp.async one full 128x128 weight into tight smem [128][128] (512 threads)
__device__ __forceinline__ void cpw(float* __restrict__ dst, const float* __restrict__ src) {
#pragma unroll
    for (int t = 0; t < 8; t++) {
        int f = threadIdx.x + t * 512;          // 0..4095 float4s
        int k = f >> 5, c = (f & 31) << 2;
        cp16(dst + k * 128 + c, src + k * 128 + c);
    }
    CP_COMMIT();
}

// ---------------------------------------------------------------------------
// Kernel 1: transpose the 7 weight matrices once into g_Wt
// ---------------------------------------------------------------------------
__global__ void transpose_weights_kernel(const float* __restrict__ Wz, const float* __restrict__ Uz,
                                         const float* __restrict__ Wr, const float* __restrict__ Ur,
                                         const float* __restrict__ Wh, const float* __restrict__ Uh,
                                         const float* __restrict__ Wp) {
    const float* src = (blockIdx.x == 0) ? Wz : (blockIdx.x == 1) ? Uz :
                       (blockIdx.x == 2) ? Wr : (blockIdx.x == 3) ? Ur :
                       (blockIdx.x == 4) ? Wh : (blockIdx.x == 5) ? Uh : Wp;
    float* dst = g_Wt + blockIdx.x * (ND * ND);
    for (int idx = threadIdx.x; idx < ND * ND; idx += blockDim.x) {
        int j = idx >> 7, k = idx & 127;
        dst[k * ND + j] = src[idx];
    }
}

// ---------------------------------------------------------------------------
// Kernel 2: hp0 = init_node @ Wp^T (one-time). 512 thr, 96-row tiles, r3c8.
// ---------------------------------------------------------------------------
#define XW_SMEM ((96 * 128 + 128 * 128) * 4)   // 114688
__global__ void __launch_bounds__(512) xw_kernel(const float* __restrict__ X,
                                                 const float* __restrict__ Wt,
                                                 float* __restrict__ out) {
    extern __shared__ float sm[];
    float* sX = sm;                 // [96][128]
    float* sW = sm + 96 * 128;      // [128][128]
    int tid = threadIdx.x;
    int tx = tid & 15, ty = tid >> 4;       // ty 0..31
    int c0 = tx * 4, r0 = ty * 3;
    long base = (long)blockIdx.x * 96;
#pragma unroll
    for (int t = 0; t < 6; t++) {
        int f = tid + t * 512;              // 0..3071 f4
        int r = f >> 5, c = (f & 31) << 2;
        cp16(sX + r * 128 + c, X + (base + r) * ND + c);
    }
#pragma unroll
    for (int t = 0; t < 8; t++) {
        int f = tid + t * 512;
        int k = f >> 5, c = (f & 31) << 2;
        cp16(sW + k * 128 + c, Wt + k * 128 + c);
    }
    CP_COMMIT();
    CP_WAIT(0); __syncthreads();
    ull acc[3][4];
    zacc<3>(acc);
    mma_t<3, 128, 128, 128>(sX, sW, r0, c0, acc);
#pragma unroll
    for (int i = 0; i < 3; i++) {
        float o[8]; row_f8(acc[i], o);
        float* orow = out + (base + r0 + i) * ND;
        *(float4*)(orow + c0)      = make_float4(o[0], o[1], o[2], o[3]);
        *(float4*)(orow + c0 + 64) = make_float4(o[4], o[5], o[6], o[7]);
    }
}

// ---------------------------------------------------------------------------
// Kernel 3: neigh[b] = mask[b] @ hp[b] + 512*Wp_b. 512 thr, 128x128 tile,
// r4c8, K=512 in 8 chunks, cp.async double-buffered. grid (4, 96).
// ---------------------------------------------------------------------------
#define MG_SMEM ((2 * 128 * 68 + 2 * 64 * 128) * 4)   // 135168
__global__ void __launch_bounds__(512) maskgemm_kernel(const float* __restrict__ mask,
                                                       const float* __restrict__ hp,
                                                       const float* __restrict__ bp,
                                                       float* __restrict__ neigh) {
    extern __shared__ float sm[];
    float* sA[2] = { sm, sm + 128 * 68 };
    float* sB[2] = { sm + 2 * 128 * 68, sm + 2 * 128 * 68 + 64 * 128 };
    int b = blockIdx.y;
    int row0g = blockIdx.x * 128;
    int tid = threadIdx.x;
    int tx = tid & 15, ty = tid >> 4;       // ty 0..31
    int c0 = tx * 4, r0 = ty * 4;
    const float* mrow = mask + ((long)b * NN + row0g) * NN;
    const float* hpb  = hp + (long)b * NN * ND;

    float bj[8];
#pragma unroll
    for (int j = 0; j < 8; j++) bj[j] = 512.0f * __ldg(bp + colof(c0, j));

    auto loadChunk = [&](int buf, int k0) {
#pragma unroll
        for (int t = 0; t < 4; t++) {          // mask 128x64: 2048 f4
            int f = tid + t * 512;
            int r = f >> 4, kq = (f & 15) << 2;
            cp16(sA[buf] + r * 68 + kq, mrow + (long)r * NN + k0 + kq);
        }
#pragma unroll
        for (int t = 0; t < 4; t++) {          // hp 64x128: 2048 f4
            int f = tid + t * 512;
            int k = f >> 5, c = (f & 31) << 2;
            cp16(sB[buf] + k * 128 + c, hpb + (long)(k0 + k) * ND + c);
        }
        CP_COMMIT();
    };

    ull acc[4][4];
    zacc<4>(acc);
    loadChunk(0, 0);
#pragma unroll 1
    for (int c = 0; c < 8; c++) {
        if (c < 7) { loadChunk((c + 1) & 1, (c + 1) * 64); CP_WAIT(1); }
        else       { CP_WAIT(0); }
        __syncthreads();
        mma_t<4, 64, 68, 128>(sA[c & 1], sB[c & 1], r0, c0, acc);
        __syncthreads();
    }
    float* orow = neigh + ((long)b * NN + row0g) * ND;
#pragma unroll
    for (int i = 0; i < 4; i++) {
        float o[8]; row_f8(acc[i], o);
#pragma unroll
        for (int j = 0; j < 8; j++) o[j] += bj[j];
        float* r = orow + (long)(r0 + i) * ND;
        *(float4*)(r + c0)      = make_float4(o[0], o[1], o[2], o[3]);
        *(float4*)(r + c0 + 64) = make_float4(o[4], o[5], o[6], o[7]);
    }
}

// ---------------------------------------------------------------------------
// Kernel 4: fused GRU. 512 thr, 96 nodes/CTA, r3c8, full-weight double buffer.
// smem: sN[96][128] (neigh->rh->h'), sH[96][128] (h), W0/W1[128][128], bias.
// ---------------------------------------------------------------------------
#define GRU_SMEM ((2 * 96 * 128 + 2 * 128 * 128 + 3 * 128) * 4)   // 230912
__global__ void __launch_bounds__(512) gru_kernel(const float* __restrict__ neigh,
                                                  const float* __restrict__ h_in,
                                                  float* __restrict__ h_out,
                                                  float* __restrict__ hp_out,
                                                  const float* __restrict__ Wt,
                                                  const float* __restrict__ Wz_b, const float* __restrict__ Uz_b,
                                                  const float* __restrict__ Wr_b, const float* __restrict__ Ur_b,
                                                  const float* __restrict__ Wh_b, const float* __restrict__ Uh_b,
                                                  int do_hp) {
    extern __shared__ float sm[];
    float* sN  = sm;                        // [96][128]
    float* sH  = sm + 96 * 128;             // [96][128]
    float* W0  = sm + 2 * 96 * 128;         // [128][128]
    float* W1  = W0 + 128 * 128;            // [128][128]
    float* sBz = W1 + 128 * 128;            // 128
    float* sBr = sBz + 128;
    float* sBh = sBr + 128;
    int tid = threadIdx.x;
    int tx = tid & 15, ty = tid >> 4;       // ty 0..31
    int c0 = tx * 4, r0 = ty * 3;
    long base = (long)blockIdx.x * 96;

    // G_A = {sN, sH, W0=Wz}; G_B = {W1=Uz}
#pragma unroll
    for (int t = 0; t < 6; t++) {
        int f = tid + t * 512;
        int r = f >> 5, c = (f & 31) << 2;
        cp16(sN + r * 128 + c, neigh + (base + r) * ND + c);
        cp16(sH + r * 128 + c, h_in + (base + r) * ND + c);
    }
#pragma unroll
    for (int t = 0; t < 8; t++) {
        int f = tid + t * 512;
        int k = f >> 5, c = (f & 31) << 2;
        cp16(W0 + k * 128 + c, Wt + k * 128 + c);       // Wz
    }
    CP_COMMIT();                            // G_A
    cpw(W1, Wt + 1 * 16384);                // G_B = Uz
    if (tid < 128) {
        sBz[tid] = Wz_b[tid] + Uz_b[tid];
        sBr[tid] = Wr_b[tid] + Ur_b[tid];
        sBh[tid] = Wh_b[tid] + Uh_b[tid];
    }

    ull acc[3][4];
    float zf[3][8], rh[3][8];

    CP_WAIT(1); __syncthreads();            // G_A: sN,sH,Wz (+bias stores fenced)
    zacc<3>(acc);
    mma_t<3, 128, 128, 128>(sN, W0, r0, c0, acc);       // z1
    __syncthreads(); cpw(W0, Wt + 2 * 16384);           // G_C = Wr
    CP_WAIT(1); __syncthreads();            // G_B: Uz
    mma_t<3, 128, 128, 128>(sH, W1, r0, c0, acc);       // z2
#pragma unroll
    for (int i = 0; i < 3; i++) {
        float o[8]; row_f8(acc[i], o);
#pragma unroll
        for (int j = 0; j < 8; j++)
            zf[i][j] = sigmoidf_(o[j] + sBz[colof(c0, j)]);
    }
    __syncthreads(); cpw(W1, Wt + 3 * 16384);           // G_D = Ur
    CP_WAIT(1); __syncthreads();            // G_C: Wr
    zacc<3>(acc);
    mma_t<3, 128, 128, 128>(sN, W0, r0, c0, acc);       // r1
    __syncthreads(); cpw(W0, Wt + 4 * 16384);           // G_E = Wh
    CP_WAIT(1); __syncthreads();            // G_D: Ur
    mma_t<3, 128, 128, 128>(sH, W1, r0, c0, acc);       // r2
#pragma unroll
    for (int i = 0; i < 3; i++) {           // park rh = sig(r)*h
        float o[8]; row_f8(acc[i], o);
#pragma unroll
        for (int j = 0; j < 8; j++) {
            int col = colof(c0, j);
            rh[i][j] = sigmoidf_(o[j] + sBr[col]) * sH[(r0 + i) * 128 + col];
        }
    }
    __syncthreads(); cpw(W1, Wt + 5 * 16384);           // G_F = Uh
    CP_WAIT(1); __syncthreads();            // G_E: Wh
    zacc<3>(acc);
    mma_t<3, 128, 128, 128>(sN, W0, r0, c0, acc);       // h1 — last sN(neigh) read
    __syncthreads();                        // h1 readers done
    cpw(W0, Wt + 6 * 16384);                // G_G = Wp
#pragma unroll
    for (int i = 0; i < 3; i++) {           // stage rh into sN (own cells)
#pragma unroll
        for (int j = 0; j < 8; j++)
            sN[(r0 + i) * 128 + colof(c0, j)] = rh[i][j];
    }
    CP_WAIT(1); __syncthreads();            // G_F: Uh ready + rh visible
    mma_t<3, 128, 128, 128>(sN, W1, r0, c0, acc);       // h2 (sN = r*h)
    __syncthreads();                        // h2 readers done
#pragma unroll
    for (int i = 0; i < 3; i++) {           // combine; write h_out; stage h'
        float o[8]; row_f8(acc[i], o);
        float hn[8];
#pragma unroll
        for (int j = 0; j < 8; j++) {
            int col = colof(c0, j);
            float hh = tanhf(o[j] + sBh[col]);
            float h = sH[(r0 + i) * 128 + col];
            hn[j] = fmaf(zf[i][j], hh - h, h);
            sN[(r0 + i) * 128 + col] = hn[j];
        }
        float* orow = h_out + (base + r0 + i) * ND;
        *(float4*)(orow + c0)      = make_float4(hn[0], hn[1], hn[2], hn[3]);
        *(float4*)(orow + c0 + 64) = make_float4(hn[4], hn[5], hn[6], hn[7]);
    }
    if (do_hp) {
        CP_WAIT(0); __syncthreads();        // G_G: Wp ready + h' visible
        zacc<3>(acc);
        mma_t<3, 128, 128, 128>(sN, W0, r0, c0, acc);   // hp = h' @ Wp^T
#pragma unroll
        for (int i = 0; i < 3; i++) {
            float o[8]; row_f8(acc[i], o);
            float* orow = hp_out + (base + r0 + i) * ND;
            *(float4*)(orow + c0)      = make_float4(o[0], o[1], o[2], o[3]);
            *(float4*)(orow + c0 + 64) = make_float4(o[4], o[5], o[6], o[7]);
        }
    } else {
        CP_WAIT(0);                         // drain ledger
    }
}

// ---------------------------------------------------------------------------
extern "C" void kernel_launch(void* const* d_in, const int* in_sizes, int n_in,
                              void* d_out, int out_size) {
    const float* init_node = (const float*)d_in[0];
    const float* mask      = (const float*)d_in[1];
    // d_in[2] = n_steps (fixed at 5 by the problem definition)
    const float* Wp_w = (const float*)d_in[3];
    const float* Wp_b = (const float*)d_in[4];
    const float* Wz_w = (const float*)d_in[5];
    const float* Wz_b = (const float*)d_in[6];
    const float* Uz_w = (const float*)d_in[7];
    const float* Uz_b = (const float*)d_in[8];
    const float* Wr_w = (const float*)d_in[9];
    const float* Wr_b = (const float*)d_in[10];
    const float* Ur_w = (const float*)d_in[11];
    const float* Ur_b = (const float*)d_in[12];
    const float* Wh_w = (const float*)d_in[13];
    const float* Wh_b = (const float*)d_in[14];
    const float* Uh_w = (const float*)d_in[15];
    const float* Uh_b = (const float*)d_in[16];
    float* hout = (float*)d_out;

    float *g_hp_p, *g_neigh_p, *g_Wt_p;
    cudaGetSymbolAddress((void**)&g_hp_p, g_hp);
    cudaGetSymbolAddress((void**)&g_neigh_p, g_neigh);
    cudaGetSymbolAddress((void**)&g_Wt_p, g_Wt);

    cudaFuncSetAttribute(gru_kernel,      cudaFuncAttributeMaxDynamicSharedMemorySize, GRU_SMEM);
    cudaFuncSetAttribute(xw_kernel,       cudaFuncAttributeMaxDynamicSharedMemorySize, XW_SMEM);
    cudaFuncSetAttribute(maskgemm_kernel, cudaFuncAttributeMaxDynamicSharedMemorySize, MG_SMEM);

    transpose_weights_kernel<<<7, 256>>>(Wz_w, Uz_w, Wr_w, Ur_w, Wh_w, Uh_w, Wp_w);
    xw_kernel<<<NROWS / 96, 512, XW_SMEM>>>(init_node, g_Wt_p + 6 * ND * ND, g_hp_p);

    for (int s = 0; s < NSTEPS; s++) {
        maskgemm_kernel<<<dim3(NN / 128, NB), 512, MG_SMEM>>>(mask, g_hp_p, Wp_b, g_neigh_p);
        gru_kernel<<<NROWS / 96, 512, GRU_SMEM>>>(
            g_neigh_p, (s == 0) ? init_node : hout, hout, g_hp_p,
            g_Wt_p, Wz_b, Uz_b, Wr_b, Ur_b, Wh_b, Uh_b, (s < NSTEPS - 1) ? 1 : 0);
    }
}